// round 10
// baseline (speedup 1.0000x reference)
#include <cuda_runtime.h>
#include <cuda_bf16.h>
#include <cstdint>

#define NNODES 100000
#define NEDGES 1600000
#define NB1 ((NNODES + 255) / 256)

typedef unsigned long long ull;

// ---------------- scratch (device globals; never passed from host) ---------
__device__ int   g_is64;
__device__ float g_deg[NNODES];
__device__ float g_dis[NNODES];
__device__ int   g_hist[NNODES];
__device__ int   g_row[NNODES + 1];
__device__ int   g_cursor[NNODES];
__device__ int   g_bsums[NB1];
__device__ int2  g_edge[NEDGES];
__device__ float g_h1[(size_t)NNODES * 128];
__device__ float g_a1[(size_t)NNODES * 128];
__device__ float g_h2[(size_t)NNODES * 64];
// W images: [hi block | lo block], each (n-major, 136 bf16 k-stride)
__device__ __nv_bfloat16 g_w1img[2 * 128 * 136];
__device__ __nv_bfloat16 g_w2img[2 * 64 * 136];

// ---------------- f32x2 helpers (agg kernels) ----------------
__device__ __forceinline__ ull dup2(float v) {
    ull r; asm("mov.b64 %0, {%1,%1};" : "=l"(r) : "r"(__float_as_uint(v))); return r;
}
__device__ __forceinline__ ull fma2(ull a, ull b, ull c) {
    ull d; asm("fma.rn.f32x2 %0, %1, %2, %3;" : "=l"(d) : "l"(a), "l"(b), "l"(c)); return d;
}
__device__ __forceinline__ float lo32(ull v) { return __uint_as_float((unsigned)v); }
__device__ __forceinline__ float hi32(ull v) { return __uint_as_float((unsigned)(v >> 32)); }

// ---------------- mma helpers (portable PTX, no 'a' features) ----------------
__device__ __forceinline__ uint32_t smem_u32(const void* p) {
    uint32_t a;
    asm("{ .reg .u64 t; cvta.to.shared.u64 t, %1; cvt.u32.u64 %0, t; }" : "=r"(a) : "l"(p));
    return a;
}
#define LDSM_X4(r, addr) \
    asm volatile("ldmatrix.sync.aligned.m8n8.x4.shared.b16 {%0,%1,%2,%3}, [%4];" \
        : "=r"((r)[0]), "=r"((r)[1]), "=r"((r)[2]), "=r"((r)[3]) : "r"(addr))
#define LDSM_X2(r, addr) \
    asm volatile("ldmatrix.sync.aligned.m8n8.x2.shared.b16 {%0,%1}, [%2];" \
        : "=r"((r)[0]), "=r"((r)[1]) : "r"(addr))
#define MMA_BF16(c, a, b) \
    asm volatile("mma.sync.aligned.m16n8k16.row.col.f32.bf16.bf16.f32 " \
        "{%0,%1,%2,%3}, {%4,%5,%6,%7}, {%8,%9}, {%0,%1,%2,%3};" \
        : "+f"((c)[0]), "+f"((c)[1]), "+f"((c)[2]), "+f"((c)[3]) \
        : "r"((a)[0]), "r"((a)[1]), "r"((a)[2]), "r"((a)[3]), \
          "r"((b)[0]), "r"((b)[1]))

__device__ __forceinline__ uint32_t pack_bf16x2(float f0, float f1) {
    uint32_t r;
    asm("cvt.rn.satfinite.bf16x2.f32 %0, %1, %2;" : "=r"(r) : "f"(f1), "f"(f0));
    return r;   // low half = bf16(f0), high half = bf16(f1)
}

// ---------------- W split/transpose into smem-image layout ----------------
__global__ void k_wsplit(const float* __restrict__ W1, const float* __restrict__ W2) {
    int t = blockIdx.x * 256 + threadIdx.x;
    if (t < 128 * 128) {                     // W1[k][n], k,n in [0,128)
        int k = t >> 7, n = t & 127;
        float f = W1[t];
        __nv_bfloat16 hb = __float2bfloat16(f);
        __nv_bfloat16 lb = __float2bfloat16(f - __bfloat162float(hb));
        g_w1img[n * 136 + k] = hb;
        g_w1img[128 * 136 + n * 136 + k] = lb;
    } else if (t < 128 * 128 + 128 * 64) {   // W2[k][n], k in [0,128), n in [0,64)
        int u = t - 128 * 128;
        int k = u >> 6, n = u & 63;
        float f = W2[u];
        __nv_bfloat16 hb = __float2bfloat16(f);
        __nv_bfloat16 lb = __float2bfloat16(f - __bfloat162float(hb));
        g_w2img[n * 136 + k] = hb;
        g_w2img[64 * 136 + n * 136 + k] = lb;
    }
}

// ---------------- init (+ fused edge_index dtype detection) ----------------
__global__ void k_init(const int* __restrict__ ei_raw) {
    int i = blockIdx.x * 256 + threadIdx.x;
    if (i < NNODES) { g_deg[i] = 1.0f; g_hist[i] = 0; }
    if (blockIdx.x == 0) {
        int bad = 0;
        for (int k = threadIdx.x; k < 2048; k += 256)
            bad |= (ei_raw[2 * k + 1] != 0);
        bad = __syncthreads_or(bad);
        if (threadIdx.x == 0) g_is64 = !bad;
    }
}

__device__ __forceinline__ void load_edge(const void* __restrict__ ei, int e,
                                          int& s, int& d) {
    if (g_is64) {
        const long long* p = (const long long*)ei;
        s = (int)p[e]; d = (int)p[NEDGES + e];
    } else {
        const int* p = (const int*)ei;
        s = p[e]; d = p[NEDGES + e];
    }
}

__global__ void k_deg(const void* __restrict__ ei, const float* __restrict__ ew) {
    int e = blockIdx.x * 256 + threadIdx.x;
    if (e < NEDGES) {
        int s, d; load_edge(ei, e, s, d);
        atomicAdd(&g_deg[d], ew[e]);
        atomicAdd(&g_hist[d], 1);
    }
}

__global__ void k_scan1() {
    __shared__ int sh[256];
    int i = blockIdx.x * 256 + threadIdx.x;
    int tid = threadIdx.x;
    if (i < NNODES) g_dis[i] = rsqrtf(g_deg[i]);
    int v = (i < NNODES) ? g_hist[i] : 0;
    sh[tid] = v; __syncthreads();
    for (int off = 1; off < 256; off <<= 1) {
        int t = (tid >= off) ? sh[tid - off] : 0;
        __syncthreads(); sh[tid] += t; __syncthreads();
    }
    if (i < NNODES) g_row[i] = sh[tid] - v;
    if (tid == 255) g_bsums[blockIdx.x] = sh[tid];
}

__global__ void k_scan2() {
    __shared__ int sh[512];
    int tid = threadIdx.x;
    int v = (tid < NB1) ? g_bsums[tid] : 0;
    sh[tid] = v; __syncthreads();
    for (int off = 1; off < 512; off <<= 1) {
        int t = (tid >= off) ? sh[tid - off] : 0;
        __syncthreads(); sh[tid] += t; __syncthreads();
    }
    if (tid < NB1) g_bsums[tid] = sh[tid] - v;
}

__global__ void k_scan3() {
    int i = blockIdx.x * 256 + threadIdx.x;
    if (i < NNODES) {
        int r = g_row[i] + g_bsums[blockIdx.x];
        g_row[i] = r;
        g_cursor[i] = r;
        if (i == 0) g_row[NNODES] = NEDGES;
    }
}

__global__ void k_sort(const void* __restrict__ ei, const float* __restrict__ ew) {
    int e = blockIdx.x * 256 + threadIdx.x;
    if (e < NEDGES) {
        int s, d; load_edge(ei, e, s, d);
        float nrm = g_dis[s] * ew[e] * g_dis[d];
        int pos = atomicAdd(&g_cursor[d], 1);
        g_edge[pos] = make_int2(s, __float_as_int(nrm));
    }
}

// ---------------- tensor-core GEMM: H[M,NCOL] = X[M,128] @ W[128,NCOL] -----
// M-tile 64, 8 warps = 4 m-strips x 2 n-halves. W staged by uint4 copy from
// the precomputed global image. X split hi/lo inline.
template<int NCOL, int LAYER>
__global__ __launch_bounds__(256) void gemm_mma(
    const float* __restrict__ Xin, int M)
{
    constexpr int STR = 272;                 // bytes per bf16 row (136 bf16)
    constexpr int XT  = 64 * STR;            // 17408 B per X tile
    constexpr int WT  = NCOL * STR;          // per hi/lo W tile
    constexpr int NF  = NCOL / 16;           // n-frags per warp (half of NCOL/8)

    extern __shared__ __align__(16) char smem[];
    char* xhi = smem;
    char* xlo = xhi + XT;
    char* whi = xlo + XT;                    // wlo = whi + WT (contiguous image)

    const float* __restrict__ X = (LAYER == 1) ? Xin : g_a1;
    float* __restrict__ H = (LAYER == 1) ? g_h1 : g_h2;

    const int tid  = threadIdx.x;
    const int lane = tid & 31;
    const int wid  = tid >> 5;
    const int row0 = blockIdx.x * 64;
    const int valid = M - row0;

    // ---- stage X (64 x 128 fp32 -> bf16 hi/lo), row-major stride 136 ----
    for (int u = tid; u < 64 * 64; u += 256) {
        int r = u >> 6, c2 = (u & 63) << 1;
        float f0 = 0.f, f1 = 0.f;
        if (r < valid) {
            float2 v = *reinterpret_cast<const float2*>(X + (size_t)(row0 + r) * 128 + c2);
            f0 = v.x; f1 = v.y;
        }
        uint32_t hp = pack_bf16x2(f0, f1);
        float h0 = __uint_as_float(hp << 16);
        float h1 = __uint_as_float(hp & 0xFFFF0000u);
        uint32_t lp = pack_bf16x2(f0 - h0, f1 - h1);
        *reinterpret_cast<uint32_t*>(xhi + r * STR + c2 * 2) = hp;
        *reinterpret_cast<uint32_t*>(xlo + r * STR + c2 * 2) = lp;
    }
    // ---- stage W: straight uint4 copy of the precomputed image ----
    {
        const uint4* wsrc = (LAYER == 1)
            ? reinterpret_cast<const uint4*>(g_w1img)
            : reinterpret_cast<const uint4*>(g_w2img);
        uint4* wdst = reinterpret_cast<uint4*>(whi);
        for (int u = tid; u < 2 * WT / 16; u += 256)
            wdst[u] = wsrc[u];
    }
    __syncthreads();

    // ---- per-lane ldmatrix base addresses ----
    const int mb = (wid & 3) * 16;           // m-strip
    const int nb = (wid >> 2) * (NCOL / 2);  // n-half
    int a_row = mb + (lane & 7) + ((lane >> 3) & 1) * 8;
    uint32_t a_off = a_row * STR + ((lane >> 4) & 1) * 16;
    uint32_t ah_base = smem_u32(xhi) + a_off;
    uint32_t al_base = smem_u32(xlo) + a_off;
    uint32_t b_off = (nb + (lane & 7)) * STR + ((lane >> 3) & 1) * 16;
    uint32_t bh_base = smem_u32(whi) + b_off;
    uint32_t bl_base = bh_base + WT;

    float c[NF][4];
#pragma unroll
    for (int nf = 0; nf < NF; nf++)
#pragma unroll
        for (int q = 0; q < 4; q++) c[nf][q] = 0.f;

#pragma unroll
    for (int ks = 0; ks < 8; ks++) {
        uint32_t ah[4], al[4];
        LDSM_X4(ah, ah_base + ks * 32);
        LDSM_X4(al, al_base + ks * 32);
#pragma unroll
        for (int nf = 0; nf < NF; nf++) {
            uint32_t bh[2], bl[2];
            LDSM_X2(bh, bh_base + nf * 8 * STR + ks * 32);
            LDSM_X2(bl, bl_base + nf * 8 * STR + ks * 32);
            MMA_BF16(c[nf], ah, bh);   // hi * hi
            MMA_BF16(c[nf], ah, bl);   // hi * lo
            MMA_BF16(c[nf], al, bh);   // lo * hi
        }
    }

    // ---- epilogue: c-frag -> H ----
    int r0 = row0 + mb + (lane >> 2);
    int cb = (lane & 3) * 2;
#pragma unroll
    for (int nf = 0; nf < NF; nf++) {
        if (r0 < M) {
            float2 v = make_float2(c[nf][0], c[nf][1]);
            *reinterpret_cast<float2*>(&H[(size_t)r0 * NCOL + nb + nf * 8 + cb]) = v;
        }
        if (r0 + 8 < M) {
            float2 v = make_float2(c[nf][2], c[nf][3]);
            *reinterpret_cast<float2*>(&H[(size_t)(r0 + 8) * NCOL + nb + nf * 8 + cb]) = v;
        }
    }
}

// ---------------- segmented aggregation (unchanged) ----------------
__global__ __launch_bounds__(256) void agg1(const float* __restrict__ bias) {
    int w = (blockIdx.x * 256 + threadIdx.x) >> 5;
    int lane = threadIdx.x & 31;
    if (w >= NNODES) return;
    const ulonglong2* H = reinterpret_cast<const ulonglong2*>(g_h1);

    int beg = g_row[w], end = g_row[w + 1];
    float ds = g_dis[w];
    ull s2 = dup2(ds * ds);
    ulonglong2 hself = H[(size_t)w * 32 + lane];
    ull acc0 = fma2(s2, hself.x, 0ull);
    ull acc1 = fma2(s2, hself.y, 0ull);

    for (int e = beg; e < end; e++) {
        int2 md = g_edge[e];
        ull nm = dup2(__int_as_float(md.y));
        ulonglong2 hv = H[(size_t)md.x * 32 + lane];
        acc0 = fma2(nm, hv.x, acc0);
        acc1 = fma2(nm, hv.y, acc1);
    }
    float4 bv = reinterpret_cast<const float4*>(bias)[lane];
    float4 o;
    o.x = fmaxf(lo32(acc0) + bv.x, 0.f);
    o.y = fmaxf(hi32(acc0) + bv.y, 0.f);
    o.z = fmaxf(lo32(acc1) + bv.z, 0.f);
    o.w = fmaxf(hi32(acc1) + bv.w, 0.f);
    reinterpret_cast<float4*>(g_a1)[(size_t)w * 32 + lane] = o;
}

__global__ __launch_bounds__(256) void agg2(const float* __restrict__ bias,
                                            float* __restrict__ out) {
    int w = (blockIdx.x * 256 + threadIdx.x) >> 5;
    int lane = threadIdx.x & 31;
    if (w >= NNODES) return;
    const ull* H = reinterpret_cast<const ull*>(g_h2);

    int beg = g_row[w], end = g_row[w + 1];
    float ds = g_dis[w];
    ull s2 = dup2(ds * ds);
    ull acc = fma2(s2, H[(size_t)w * 32 + lane], 0ull);

    for (int e = beg; e < end; e++) {
        int2 md = g_edge[e];
        ull nm = dup2(__int_as_float(md.y));
        acc = fma2(nm, H[(size_t)md.x * 32 + lane], acc);
    }
    float2 bv = reinterpret_cast<const float2*>(bias)[lane];
    float2 o;
    o.x = lo32(acc) + bv.x;
    o.y = hi32(acc) + bv.y;
    reinterpret_cast<float2*>(out)[(size_t)w * 32 + lane] = o;
}

// ---------------- launch ----------------
extern "C" void kernel_launch(void* const* d_in, const int* in_sizes, int n_in,
                              void* d_out, int out_size)
{
    const float* x  = (const float*)d_in[0];
    const void*  ei = d_in[1];
    const float* ew = (const float*)d_in[2];
    const float* W1 = (const float*)d_in[3];
    const float* b1 = (const float*)d_in[4];
    const float* W2 = (const float*)d_in[5];
    const float* b2 = (const float*)d_in[6];
    float* out = (float*)d_out;

    const int nb_nodes = (NNODES + 255) / 256;
    const int nb_edges = (NEDGES + 255) / 256;
    const int nb_rows  = (NNODES + 63) / 64;     // 1563
    const int nb_warps = (NNODES * 32 + 255) / 256;

    constexpr int SM1 = 2 * (64 * 272) + 2 * (128 * 272);  // 104448 -> 2 blk/SM
    constexpr int SM2 = 2 * (64 * 272) + 2 * (64 * 272);   // 69632  -> 3 blk/SM
    cudaFuncSetAttribute(gemm_mma<128, 1>, cudaFuncAttributeMaxDynamicSharedMemorySize, SM1);
    cudaFuncSetAttribute(gemm_mma<64, 2>,  cudaFuncAttributeMaxDynamicSharedMemorySize, SM2);

    k_wsplit<<<96, 256>>>(W1, W2);                            // 0
    k_init<<<nb_nodes, 256>>>((const int*)ei);                // 1
    k_deg<<<nb_edges, 256>>>(ei, ew);                         // 2
    gemm_mma<128, 1><<<nb_rows, 256, SM1>>>(x, NNODES);       // 3  <- profiled
    k_scan1<<<nb_nodes, 256>>>();                             // 4
    k_scan2<<<1, 512>>>();                                    // 5
    k_scan3<<<nb_nodes, 256>>>();                             // 6
    k_sort<<<nb_edges, 256>>>(ei, ew);                        // 7
    agg1<<<nb_warps, 256>>>(b1);                              // 8
    gemm_mma<64, 2><<<nb_rows, 256, SM2>>>(nullptr, NNODES);  // 9
    agg2<<<nb_warps, 256>>>(b2, out);                         // 10
}

// round 11
// speedup vs baseline: 1.2387x; 1.2387x over previous
#include <cuda_runtime.h>
#include <cuda_fp16.h>
#include <cstdint>

#define NNODES 100000
#define NEDGES 1600000
#define NB1 ((NNODES + 255) / 256)

typedef unsigned long long ull;

// ---------------- scratch (device globals; never passed from host) ---------
__device__ int   g_is64;
__device__ float g_deg[NNODES];
__device__ float g_dis[NNODES];
__device__ int   g_hist[NNODES];
__device__ int   g_row[NNODES + 1];
__device__ int   g_cursor[NNODES];
__device__ int   g_bsums[NB1];
__device__ int2  g_edge[NEDGES];
__device__ float g_h1[(size_t)NNODES * 128];
__device__ float g_a1[(size_t)NNODES * 128];
__device__ float g_h2[(size_t)NNODES * 64];
// fp16 W images: n-major, k-stride 136 halves (272 B)
__device__ __half g_w1img[128 * 136];
__device__ __half g_w2img[64 * 136];

// ---------------- f32x2 helpers (agg kernels) ----------------
__device__ __forceinline__ ull dup2(float v) {
    ull r; asm("mov.b64 %0, {%1,%1};" : "=l"(r) : "r"(__float_as_uint(v))); return r;
}
__device__ __forceinline__ ull fma2(ull a, ull b, ull c) {
    ull d; asm("fma.rn.f32x2 %0, %1, %2, %3;" : "=l"(d) : "l"(a), "l"(b), "l"(c)); return d;
}
__device__ __forceinline__ float lo32(ull v) { return __uint_as_float((unsigned)v); }
__device__ __forceinline__ float hi32(ull v) { return __uint_as_float((unsigned)(v >> 32)); }

// ---------------- mma helpers (portable PTX, no 'a' features) ----------------
__device__ __forceinline__ uint32_t smem_u32(const void* p) {
    uint32_t a;
    asm("{ .reg .u64 t; cvta.to.shared.u64 t, %1; cvt.u32.u64 %0, t; }" : "=r"(a) : "l"(p));
    return a;
}
#define LDSM_X4(r, addr) \
    asm volatile("ldmatrix.sync.aligned.m8n8.x4.shared.b16 {%0,%1,%2,%3}, [%4];" \
        : "=r"((r)[0]), "=r"((r)[1]), "=r"((r)[2]), "=r"((r)[3]) : "r"(addr))
#define MMA_F16(c, a, b0, b1) \
    asm volatile("mma.sync.aligned.m16n8k16.row.col.f32.f16.f16.f32 " \
        "{%0,%1,%2,%3}, {%4,%5,%6,%7}, {%8,%9}, {%0,%1,%2,%3};" \
        : "+f"((c)[0]), "+f"((c)[1]), "+f"((c)[2]), "+f"((c)[3]) \
        : "r"((a)[0]), "r"((a)[1]), "r"((a)[2]), "r"((a)[3]), \
          "r"(b0), "r"(b1))

__device__ __forceinline__ uint32_t pack_f16x2(float f0, float f1) {
    uint32_t r;
    asm("cvt.rn.f16x2.f32 %0, %1, %2;" : "=r"(r) : "f"(f1), "f"(f0));
    return r;   // low half = f16(f0), high half = f16(f1)
}

// ---------------- W convert/transpose into fp16 image ----------------
__global__ void k_wconv(const float* __restrict__ W1, const float* __restrict__ W2) {
    int t = blockIdx.x * 256 + threadIdx.x;
    if (t < 128 * 128) {                     // W1[k][n]
        int k = t >> 7, n = t & 127;
        g_w1img[n * 136 + k] = __float2half(W1[t]);
    } else if (t < 128 * 128 + 128 * 64) {   // W2[k][n]
        int u = t - 128 * 128;
        int k = u >> 6, n = u & 63;
        g_w2img[n * 136 + k] = __float2half(W2[u]);
    }
}

// ---------------- init (+ fused edge_index dtype detection) ----------------
__global__ void k_init(const int* __restrict__ ei_raw) {
    int i = blockIdx.x * 256 + threadIdx.x;
    if (i < NNODES) { g_deg[i] = 1.0f; g_hist[i] = 0; }
    if (blockIdx.x == 0) {
        int bad = 0;
        for (int k = threadIdx.x; k < 2048; k += 256)
            bad |= (ei_raw[2 * k + 1] != 0);
        bad = __syncthreads_or(bad);
        if (threadIdx.x == 0) g_is64 = !bad;
    }
}

__device__ __forceinline__ void load_edge(const void* __restrict__ ei, int e,
                                          int& s, int& d) {
    if (g_is64) {
        const long long* p = (const long long*)ei;
        s = (int)p[e]; d = (int)p[NEDGES + e];
    } else {
        const int* p = (const int*)ei;
        s = p[e]; d = p[NEDGES + e];
    }
}

__global__ void k_deg(const void* __restrict__ ei, const float* __restrict__ ew) {
    int e = blockIdx.x * 256 + threadIdx.x;
    if (e < NEDGES) {
        int s, d; load_edge(ei, e, s, d);
        atomicAdd(&g_deg[d], ew[e]);
        atomicAdd(&g_hist[d], 1);
    }
}

__global__ void k_scan1() {
    __shared__ int sh[256];
    int i = blockIdx.x * 256 + threadIdx.x;
    int tid = threadIdx.x;
    if (i < NNODES) g_dis[i] = rsqrtf(g_deg[i]);
    int v = (i < NNODES) ? g_hist[i] : 0;
    sh[tid] = v; __syncthreads();
    for (int off = 1; off < 256; off <<= 1) {
        int t = (tid >= off) ? sh[tid - off] : 0;
        __syncthreads(); sh[tid] += t; __syncthreads();
    }
    if (i < NNODES) g_row[i] = sh[tid] - v;
    if (tid == 255) g_bsums[blockIdx.x] = sh[tid];
}

__global__ void k_scan2() {
    __shared__ int sh[512];
    int tid = threadIdx.x;
    int v = (tid < NB1) ? g_bsums[tid] : 0;
    sh[tid] = v; __syncthreads();
    for (int off = 1; off < 512; off <<= 1) {
        int t = (tid >= off) ? sh[tid - off] : 0;
        __syncthreads(); sh[tid] += t; __syncthreads();
    }
    if (tid < NB1) g_bsums[tid] = sh[tid] - v;
}

__global__ void k_scan3() {
    int i = blockIdx.x * 256 + threadIdx.x;
    if (i < NNODES) {
        int r = g_row[i] + g_bsums[blockIdx.x];
        g_row[i] = r;
        g_cursor[i] = r;
        if (i == 0) g_row[NNODES] = NEDGES;
    }
}

__global__ void k_sort(const void* __restrict__ ei, const float* __restrict__ ew) {
    int e = blockIdx.x * 256 + threadIdx.x;
    if (e < NEDGES) {
        int s, d; load_edge(ei, e, s, d);
        float nrm = g_dis[s] * ew[e] * g_dis[d];
        int pos = atomicAdd(&g_cursor[d], 1);
        g_edge[pos] = make_int2(s, __float_as_int(nrm));
    }
}

// ---------------- tensor-core GEMM (fp16 1-pass): H = X @ W ----------------
// M-tile 128, 8 warps = 8 m-strips of 16 rows, full NCOL per warp.
// B-fragments: two n-frags per ldmatrix.x4.
template<int NCOL, int LAYER>
__global__ __launch_bounds__(256, 2) void gemm_mma(
    const float* __restrict__ Xin, int M)
{
    constexpr int STR = 272;                 // bytes per fp16 row (136 halves)
    constexpr int XT  = 128 * STR;           // 34816 B X tile
    constexpr int WT  = NCOL * STR;          // W tile bytes
    constexpr int NF  = NCOL / 8;            // n-frags per warp (16 or 8)

    extern __shared__ __align__(16) char smem[];
    char* xs = smem;
    char* ws = xs + XT;

    const float* __restrict__ X = (LAYER == 1) ? Xin : g_a1;
    float* __restrict__ H = (LAYER == 1) ? g_h1 : g_h2;

    const int tid  = threadIdx.x;
    const int lane = tid & 31;
    const int wid  = tid >> 5;
    const int row0 = blockIdx.x * 128;
    const int valid = M - row0;

    // ---- stage X (128 x 128 fp32 -> fp16), row-major stride 136 halves ----
    for (int u = tid; u < 128 * 32; u += 256) {
        int r = u >> 5, c4 = u & 31;         // c4: which float4 of the row
        float4 v = make_float4(0.f, 0.f, 0.f, 0.f);
        if (r < valid)
            v = reinterpret_cast<const float4*>(X)[(size_t)(row0 + r) * 32 + c4];
        uint2 p;
        p.x = pack_f16x2(v.x, v.y);
        p.y = pack_f16x2(v.z, v.w);
        *reinterpret_cast<uint2*>(xs + r * STR + c4 * 8) = p;
    }
    // ---- stage W: straight uint4 copy of the precomputed fp16 image ----
    {
        const uint4* wsrc = (LAYER == 1)
            ? reinterpret_cast<const uint4*>(g_w1img)
            : reinterpret_cast<const uint4*>(g_w2img);
        uint4* wdst = reinterpret_cast<uint4*>(ws);
        for (int u = tid; u < WT / 16; u += 256)
            wdst[u] = wsrc[u];
    }
    __syncthreads();

    // ---- per-lane ldmatrix base addresses ----
    const int mb = wid * 16;
    int a_row = mb + (lane & 7) + ((lane >> 3) & 1) * 8;
    uint32_t ah_base = smem_u32(xs) + a_row * STR + ((lane >> 4) & 1) * 16;
    // B x4: lanes 0-7 -> nf even k-lo, 8-15 -> nf even k-hi,
    //       16-23 -> nf odd k-lo, 24-31 -> nf odd k-hi
    uint32_t b_base = smem_u32(ws)
                    + (((lane >> 4) & 1) * 8 + (lane & 7)) * STR
                    + ((lane >> 3) & 1) * 16;

    float c[NF][4];
#pragma unroll
    for (int nf = 0; nf < NF; nf++)
#pragma unroll
        for (int q = 0; q < 4; q++) c[nf][q] = 0.f;

#pragma unroll
    for (int ks = 0; ks < 8; ks++) {
        uint32_t a[4];
        LDSM_X4(a, ah_base + ks * 32);
#pragma unroll
        for (int np = 0; np < NF / 2; np++) {
            uint32_t b[4];
            LDSM_X4(b, b_base + np * 16 * STR + ks * 32);
            MMA_F16(c[2 * np],     a, b[0], b[1]);
            MMA_F16(c[2 * np + 1], a, b[2], b[3]);
        }
    }

    // ---- epilogue: c-frag -> H ----
    int r0 = row0 + mb + (lane >> 2);
    int cb = (lane & 3) * 2;
#pragma unroll
    for (int nf = 0; nf < NF; nf++) {
        if (r0 < M) {
            float2 v = make_float2(c[nf][0], c[nf][1]);
            *reinterpret_cast<float2*>(&H[(size_t)r0 * NCOL + nf * 8 + cb]) = v;
        }
        if (r0 + 8 < M) {
            float2 v = make_float2(c[nf][2], c[nf][3]);
            *reinterpret_cast<float2*>(&H[(size_t)(r0 + 8) * NCOL + nf * 8 + cb]) = v;
        }
    }
}

// ---------------- segmented aggregation (unchanged) ----------------
__global__ __launch_bounds__(256) void agg1(const float* __restrict__ bias) {
    int w = (blockIdx.x * 256 + threadIdx.x) >> 5;
    int lane = threadIdx.x & 31;
    if (w >= NNODES) return;
    const ulonglong2* H = reinterpret_cast<const ulonglong2*>(g_h1);

    int beg = g_row[w], end = g_row[w + 1];
    float ds = g_dis[w];
    ull s2 = dup2(ds * ds);
    ulonglong2 hself = H[(size_t)w * 32 + lane];
    ull acc0 = fma2(s2, hself.x, 0ull);
    ull acc1 = fma2(s2, hself.y, 0ull);

    for (int e = beg; e < end; e++) {
        int2 md = g_edge[e];
        ull nm = dup2(__int_as_float(md.y));
        ulonglong2 hv = H[(size_t)md.x * 32 + lane];
        acc0 = fma2(nm, hv.x, acc0);
        acc1 = fma2(nm, hv.y, acc1);
    }
    float4 bv = reinterpret_cast<const float4*>(bias)[lane];
    float4 o;
    o.x = fmaxf(lo32(acc0) + bv.x, 0.f);
    o.y = fmaxf(hi32(acc0) + bv.y, 0.f);
    o.z = fmaxf(lo32(acc1) + bv.z, 0.f);
    o.w = fmaxf(hi32(acc1) + bv.w, 0.f);
    reinterpret_cast<float4*>(g_a1)[(size_t)w * 32 + lane] = o;
}

__global__ __launch_bounds__(256) void agg2(const float* __restrict__ bias,
                                            float* __restrict__ out) {
    int w = (blockIdx.x * 256 + threadIdx.x) >> 5;
    int lane = threadIdx.x & 31;
    if (w >= NNODES) return;
    const ull* H = reinterpret_cast<const ull*>(g_h2);

    int beg = g_row[w], end = g_row[w + 1];
    float ds = g_dis[w];
    ull s2 = dup2(ds * ds);
    ull acc = fma2(s2, H[(size_t)w * 32 + lane], 0ull);

    for (int e = beg; e < end; e++) {
        int2 md = g_edge[e];
        ull nm = dup2(__int_as_float(md.y));
        acc = fma2(nm, H[(size_t)md.x * 32 + lane], acc);
    }
    float2 bv = reinterpret_cast<const float2*>(bias)[lane];
    float2 o;
    o.x = lo32(acc) + bv.x;
    o.y = hi32(acc) + bv.y;
    reinterpret_cast<float2*>(out)[(size_t)w * 32 + lane] = o;
}

// ---------------- launch ----------------
extern "C" void kernel_launch(void* const* d_in, const int* in_sizes, int n_in,
                              void* d_out, int out_size)
{
    const float* x  = (const float*)d_in[0];
    const void*  ei = d_in[1];
    const float* ew = (const float*)d_in[2];
    const float* W1 = (const float*)d_in[3];
    const float* b1 = (const float*)d_in[4];
    const float* W2 = (const float*)d_in[5];
    const float* b2 = (const float*)d_in[6];
    float* out = (float*)d_out;

    const int nb_nodes = (NNODES + 255) / 256;
    const int nb_edges = (NEDGES + 255) / 256;
    const int nb_rows  = (NNODES + 127) / 128;   // 782
    const int nb_warps = (NNODES * 32 + 255) / 256;

    constexpr int SM1 = 128 * 272 + 128 * 272;   // 69632 B -> 2+ blk/SM
    constexpr int SM2 = 128 * 272 + 64 * 272;    // 52224 B
    cudaFuncSetAttribute(gemm_mma<128, 1>, cudaFuncAttributeMaxDynamicSharedMemorySize, SM1);
    cudaFuncSetAttribute(gemm_mma<64, 2>,  cudaFuncAttributeMaxDynamicSharedMemorySize, SM2);

    k_wconv<<<96, 256>>>(W1, W2);                             // 0
    k_init<<<nb_nodes, 256>>>((const int*)ei);                // 1
    k_deg<<<nb_edges, 256>>>(ei, ew);                         // 2
    gemm_mma<128, 1><<<nb_rows, 256, SM1>>>(x, NNODES);       // 3  <- profiled
    k_scan1<<<nb_nodes, 256>>>();                             // 4
    k_scan2<<<1, 512>>>();                                    // 5
    k_scan3<<<nb_nodes, 256>>>();                             // 6
    k_sort<<<nb_edges, 256>>>(ei, ew);                        // 7
    agg1<<<nb_warps, 256>>>(b1);                              // 8
    gemm_mma<64, 2><<<nb_rows, 256, SM2>>>(nullptr, NNODES);  // 9
    agg2<<<nb_warps, 256>>>(b2, out);                         // 10
}

// round 12
// speedup vs baseline: 1.4961x; 1.2078x over previous
#include <cuda_runtime.h>
#include <cuda_fp16.h>
#include <cstdint>

#define NNODES 100000
#define NEDGES 1600000
#define NB1 ((NNODES + 255) / 256)

typedef unsigned long long ull;

// ---------------- scratch (device globals; never passed from host) ---------
__device__ int   g_is64;
__device__ float g_deg[NNODES];
__device__ float g_dis[NNODES];
__device__ int   g_hist[NNODES];
__device__ int   g_row[NNODES + 1];
__device__ int   g_cursor[NNODES];
__device__ int   g_bsums[NB1];
__device__ int2  g_edge[NEDGES];
__device__ __half g_h1h[(size_t)NNODES * 128];   // layer-1 GEMM out (fp16)
__device__ __half g_a1h[(size_t)NNODES * 128];   // relu(agg1) = layer-2 input (fp16)
__device__ __half g_h2h[(size_t)NNODES * 64];    // layer-2 GEMM out (fp16)
// fp16 W images: n-major, k-stride 136 halves (272 B)
__device__ __half g_w1img[128 * 136];
__device__ __half g_w2img[64 * 136];

// ---------------- mma helpers (portable PTX, no 'a' features) ----------------
__device__ __forceinline__ uint32_t smem_u32(const void* p) {
    uint32_t a;
    asm("{ .reg .u64 t; cvta.to.shared.u64 t, %1; cvt.u32.u64 %0, t; }" : "=r"(a) : "l"(p));
    return a;
}
#define LDSM_X4(r, addr) \
    asm volatile("ldmatrix.sync.aligned.m8n8.x4.shared.b16 {%0,%1,%2,%3}, [%4];" \
        : "=r"((r)[0]), "=r"((r)[1]), "=r"((r)[2]), "=r"((r)[3]) : "r"(addr))
#define MMA_F16(c, a, b0, b1) \
    asm volatile("mma.sync.aligned.m16n8k16.row.col.f32.f16.f16.f32 " \
        "{%0,%1,%2,%3}, {%4,%5,%6,%7}, {%8,%9}, {%0,%1,%2,%3};" \
        : "+f"((c)[0]), "+f"((c)[1]), "+f"((c)[2]), "+f"((c)[3]) \
        : "r"((a)[0]), "r"((a)[1]), "r"((a)[2]), "r"((a)[3]), \
          "r"(b0), "r"(b1))

__device__ __forceinline__ uint32_t pack_f16x2(float f0, float f1) {
    uint32_t r;
    asm("cvt.rn.f16x2.f32 %0, %1, %2;" : "=r"(r) : "f"(f1), "f"(f0));
    return r;   // low half = f16(f0), high half = f16(f1)
}

// ---------------- W convert/transpose into fp16 image ----------------
__global__ void k_wconv(const float* __restrict__ W1, const float* __restrict__ W2) {
    int t = blockIdx.x * 256 + threadIdx.x;
    if (t < 128 * 128) {                     // W1[k][n]
        int k = t >> 7, n = t & 127;
        g_w1img[n * 136 + k] = __float2half(W1[t]);
    } else if (t < 128 * 128 + 128 * 64) {   // W2[k][n]
        int u = t - 128 * 128;
        int k = u >> 6, n = u & 63;
        g_w2img[n * 136 + k] = __float2half(W2[u]);
    }
}

// ---------------- init (+ fused edge_index dtype detection) ----------------
__global__ void k_init(const int* __restrict__ ei_raw) {
    int i = blockIdx.x * 256 + threadIdx.x;
    if (i < NNODES) { g_deg[i] = 1.0f; g_hist[i] = 0; }
    if (blockIdx.x == 0) {
        int bad = 0;
        for (int k = threadIdx.x; k < 2048; k += 256)
            bad |= (ei_raw[2 * k + 1] != 0);
        bad = __syncthreads_or(bad);
        if (threadIdx.x == 0) g_is64 = !bad;
    }
}

__device__ __forceinline__ void load_edge(const void* __restrict__ ei, int e,
                                          int& s, int& d) {
    if (g_is64) {
        const long long* p = (const long long*)ei;
        s = (int)p[e]; d = (int)p[NEDGES + e];
    } else {
        const int* p = (const int*)ei;
        s = p[e]; d = p[NEDGES + e];
    }
}

__global__ void k_deg(const void* __restrict__ ei, const float* __restrict__ ew) {
    int e = blockIdx.x * 256 + threadIdx.x;
    if (e < NEDGES) {
        int s, d; load_edge(ei, e, s, d);
        atomicAdd(&g_deg[d], ew[e]);
        atomicAdd(&g_hist[d], 1);
    }
}

__global__ void k_scan1() {
    __shared__ int sh[256];
    int i = blockIdx.x * 256 + threadIdx.x;
    int tid = threadIdx.x;
    if (i < NNODES) g_dis[i] = rsqrtf(g_deg[i]);
    int v = (i < NNODES) ? g_hist[i] : 0;
    sh[tid] = v; __syncthreads();
    for (int off = 1; off < 256; off <<= 1) {
        int t = (tid >= off) ? sh[tid - off] : 0;
        __syncthreads(); sh[tid] += t; __syncthreads();
    }
    if (i < NNODES) g_row[i] = sh[tid] - v;
    if (tid == 255) g_bsums[blockIdx.x] = sh[tid];
}

__global__ void k_scan2() {
    __shared__ int sh[512];
    int tid = threadIdx.x;
    int v = (tid < NB1) ? g_bsums[tid] : 0;
    sh[tid] = v; __syncthreads();
    for (int off = 1; off < 512; off <<= 1) {
        int t = (tid >= off) ? sh[tid - off] : 0;
        __syncthreads(); sh[tid] += t; __syncthreads();
    }
    if (tid < NB1) g_bsums[tid] = sh[tid] - v;
}

__global__ void k_scan3() {
    int i = blockIdx.x * 256 + threadIdx.x;
    if (i < NNODES) {
        int r = g_row[i] + g_bsums[blockIdx.x];
        g_row[i] = r;
        g_cursor[i] = r;
        if (i == 0) g_row[NNODES] = NEDGES;
    }
}

__global__ void k_sort(const void* __restrict__ ei, const float* __restrict__ ew) {
    int e = blockIdx.x * 256 + threadIdx.x;
    if (e < NEDGES) {
        int s, d; load_edge(ei, e, s, d);
        float nrm = g_dis[s] * ew[e] * g_dis[d];
        int pos = atomicAdd(&g_cursor[d], 1);
        g_edge[pos] = make_int2(s, __float_as_int(nrm));
    }
}

// ---------------- tensor-core GEMM (fp16 1-pass): H = X @ W ----------------
// M-tile 128, 8 warps = 8 m-strips of 16 rows, full NCOL per warp.
// LAYER 1: X = fp32 input, cvt at stage.  LAYER 2: X = g_a1h (already fp16).
// H written as fp16 (packed half2 stores).
template<int NCOL, int LAYER>
__global__ __launch_bounds__(256, 2) void gemm_mma(
    const float* __restrict__ Xin, int M)
{
    constexpr int STR = 272;                 // bytes per fp16 row (136 halves)
    constexpr int XT  = 128 * STR;           // 34816 B X tile
    constexpr int WT  = NCOL * STR;          // W tile bytes
    constexpr int NF  = NCOL / 8;            // n-frags per warp (16 or 8)

    extern __shared__ __align__(16) char smem[];
    char* xs = smem;
    char* ws = xs + XT;

    __half* __restrict__ H = (LAYER == 1) ? g_h1h : g_h2h;

    const int tid  = threadIdx.x;
    const int lane = tid & 31;
    const int wid  = tid >> 5;
    const int row0 = blockIdx.x * 128;
    const int valid = M - row0;

    if (LAYER == 1) {
        // stage X: fp32 -> fp16, row-major stride 136 halves
        for (int u = tid; u < 128 * 32; u += 256) {
            int r = u >> 5, c4 = u & 31;
            float4 v = make_float4(0.f, 0.f, 0.f, 0.f);
            if (r < valid)
                v = reinterpret_cast<const float4*>(Xin)[(size_t)(row0 + r) * 32 + c4];
            uint2 p;
            p.x = pack_f16x2(v.x, v.y);
            p.y = pack_f16x2(v.z, v.w);
            *reinterpret_cast<uint2*>(xs + r * STR + c4 * 8) = p;
        }
    } else {
        // stage X: already fp16 in g_a1h — pure uint4 copy (row = 16 uint4)
        const uint4* A = reinterpret_cast<const uint4*>(g_a1h);
        for (int u = tid; u < 128 * 16; u += 256) {
            int r = u >> 4, c = u & 15;
            uint4 v = make_uint4(0u, 0u, 0u, 0u);
            if (r < valid)
                v = A[(size_t)(row0 + r) * 16 + c];
            *reinterpret_cast<uint4*>(xs + r * STR + c * 16) = v;
        }
    }
    // stage W: straight uint4 copy of the precomputed fp16 image
    {
        const uint4* wsrc = (LAYER == 1)
            ? reinterpret_cast<const uint4*>(g_w1img)
            : reinterpret_cast<const uint4*>(g_w2img);
        uint4* wdst = reinterpret_cast<uint4*>(ws);
        for (int u = tid; u < WT / 16; u += 256)
            wdst[u] = wsrc[u];
    }
    __syncthreads();

    // ---- per-lane ldmatrix base addresses ----
    const int mb = wid * 16;
    int a_row = mb + (lane & 7) + ((lane >> 3) & 1) * 8;
    uint32_t ah_base = smem_u32(xs) + a_row * STR + ((lane >> 4) & 1) * 16;
    uint32_t b_base = smem_u32(ws)
                    + (((lane >> 4) & 1) * 8 + (lane & 7)) * STR
                    + ((lane >> 3) & 1) * 16;

    float c[NF][4];
#pragma unroll
    for (int nf = 0; nf < NF; nf++)
#pragma unroll
        for (int q = 0; q < 4; q++) c[nf][q] = 0.f;

#pragma unroll
    for (int ks = 0; ks < 8; ks++) {
        uint32_t a[4];
        LDSM_X4(a, ah_base + ks * 32);
#pragma unroll
        for (int np = 0; np < NF / 2; np++) {
            uint32_t b[4];
            LDSM_X4(b, b_base + np * 16 * STR + ks * 32);
            MMA_F16(c[2 * np],     a, b[0], b[1]);
            MMA_F16(c[2 * np + 1], a, b[2], b[3]);
        }
    }

    // ---- epilogue: c-frag -> H (fp16, packed half2 stores) ----
    uint32_t* Hu = reinterpret_cast<uint32_t*>(H);
    int r0 = row0 + mb + (lane >> 2);
    int cq = lane & 3;                        // half2 index within n-frag
#pragma unroll
    for (int nf = 0; nf < NF; nf++) {
        if (r0 < M)
            Hu[(size_t)r0 * (NCOL / 2) + nf * 4 + cq] = pack_f16x2(c[nf][0], c[nf][1]);
        if (r0 + 8 < M)
            Hu[(size_t)(r0 + 8) * (NCOL / 2) + nf * 4 + cq] = pack_f16x2(c[nf][2], c[nf][3]);
    }
}

// ---------------- segmented aggregation: one warp per dst node --------------
// a1[d] = relu( b1 + dis[d]^2*h1[d] + sum_e norm_e * h1[src_e] ),  C=128 fp16
__global__ __launch_bounds__(256) void agg1(const float* __restrict__ bias) {
    int w = (blockIdx.x * 256 + threadIdx.x) >> 5;
    int lane = threadIdx.x & 31;
    if (w >= NNODES) return;
    const uint2* H = reinterpret_cast<const uint2*>(g_h1h);  // 32 uint2 per row

    int beg = g_row[w], end = g_row[w + 1];
    float ds = g_dis[w];
    float s2 = ds * ds;

    uint2 hv = H[(size_t)w * 32 + lane];
    float2 f0 = __half22float2(*reinterpret_cast<__half2*>(&hv.x));
    float2 f1 = __half22float2(*reinterpret_cast<__half2*>(&hv.y));
    float a0 = s2 * f0.x, a1 = s2 * f0.y, a2 = s2 * f1.x, a3 = s2 * f1.y;

    for (int e = beg; e < end; e++) {
        int2 md = g_edge[e];
        float nm = __int_as_float(md.y);
        uint2 v = H[(size_t)md.x * 32 + lane];
        float2 g0 = __half22float2(*reinterpret_cast<__half2*>(&v.x));
        float2 g1 = __half22float2(*reinterpret_cast<__half2*>(&v.y));
        a0 = fmaf(nm, g0.x, a0);
        a1 = fmaf(nm, g0.y, a1);
        a2 = fmaf(nm, g1.x, a2);
        a3 = fmaf(nm, g1.y, a3);
    }
    float4 bv = reinterpret_cast<const float4*>(bias)[lane];
    a0 = fmaxf(a0 + bv.x, 0.f);
    a1 = fmaxf(a1 + bv.y, 0.f);
    a2 = fmaxf(a2 + bv.z, 0.f);
    a3 = fmaxf(a3 + bv.w, 0.f);
    uint2 o;
    o.x = pack_f16x2(a0, a1);
    o.y = pack_f16x2(a2, a3);
    reinterpret_cast<uint2*>(g_a1h)[(size_t)w * 32 + lane] = o;
}

// out[d] = b2 + dis[d]^2*h2[d] + sum_e norm_e * h2[src_e],  C=64 fp16 -> fp32
__global__ __launch_bounds__(256) void agg2(const float* __restrict__ bias,
                                            float* __restrict__ out) {
    int w = (blockIdx.x * 256 + threadIdx.x) >> 5;
    int lane = threadIdx.x & 31;
    if (w >= NNODES) return;
    const uint32_t* H = reinterpret_cast<const uint32_t*>(g_h2h);  // 32 u32 per row

    int beg = g_row[w], end = g_row[w + 1];
    float ds = g_dis[w];
    float s2 = ds * ds;

    uint32_t hv = H[(size_t)w * 32 + lane];
    float2 f = __half22float2(*reinterpret_cast<__half2*>(&hv));
    float a0 = s2 * f.x, a1 = s2 * f.y;

    for (int e = beg; e < end; e++) {
        int2 md = g_edge[e];
        float nm = __int_as_float(md.y);
        uint32_t v = H[(size_t)md.x * 32 + lane];
        float2 g = __half22float2(*reinterpret_cast<__half2*>(&v));
        a0 = fmaf(nm, g.x, a0);
        a1 = fmaf(nm, g.y, a1);
    }
    float2 bv = reinterpret_cast<const float2*>(bias)[lane];
    float2 o = make_float2(a0 + bv.x, a1 + bv.y);
    reinterpret_cast<float2*>(out)[(size_t)w * 32 + lane] = o;
}

// ---------------- launch ----------------
extern "C" void kernel_launch(void* const* d_in, const int* in_sizes, int n_in,
                              void* d_out, int out_size)
{
    const float* x  = (const float*)d_in[0];
    const void*  ei = d_in[1];
    const float* ew = (const float*)d_in[2];
    const float* W1 = (const float*)d_in[3];
    const float* b1 = (const float*)d_in[4];
    const float* W2 = (const float*)d_in[5];
    const float* b2 = (const float*)d_in[6];
    float* out = (float*)d_out;

    const int nb_nodes = (NNODES + 255) / 256;
    const int nb_edges = (NEDGES + 255) / 256;
    const int nb_rows  = (NNODES + 127) / 128;   // 782
    const int nb_warps = (NNODES * 32 + 255) / 256;

    constexpr int SM1 = 128 * 272 + 128 * 272;   // 69632 B
    constexpr int SM2 = 128 * 272 + 64 * 272;    // 52224 B
    cudaFuncSetAttribute(gemm_mma<128, 1>, cudaFuncAttributeMaxDynamicSharedMemorySize, SM1);
    cudaFuncSetAttribute(gemm_mma<64, 2>,  cudaFuncAttributeMaxDynamicSharedMemorySize, SM2);

    k_wconv<<<96, 256>>>(W1, W2);                             // 0
    k_init<<<nb_nodes, 256>>>((const int*)ei);                // 1
    k_deg<<<nb_edges, 256>>>(ei, ew);                         // 2
    gemm_mma<128, 1><<<nb_rows, 256, SM1>>>(x, NNODES);       // 3  <- profiled
    k_scan1<<<nb_nodes, 256>>>();                             // 4
    k_scan2<<<1, 512>>>();                                    // 5
    k_scan3<<<nb_nodes, 256>>>();                             // 6
    k_sort<<<nb_edges, 256>>>(ei, ew);                        // 7
    agg1<<<nb_warps, 256>>>(b1);                              // 8
    gemm_mma<64, 2><<<nb_rows, 256, SM2>>>(nullptr, NNODES);  // 9
    agg2<<<nb_warps, 256>>>(b2, out);                         // 10
}

// round 13
// speedup vs baseline: 1.5828x; 1.0579x over previous
#include <cuda_runtime.h>
#include <cuda_fp16.h>
#include <cstdint>

#define NNODES 100000
#define NEDGES 1600000
#define NB1 ((NNODES + 255) / 256)

// ---------------- scratch (device globals; never passed from host) ---------
__device__ int   g_is64;
__device__ float g_deg[NNODES];
__device__ float g_dis[NNODES];
__device__ int   g_hist[NNODES];
__device__ int   g_row[NNODES + 1];
__device__ int   g_cursor[NNODES];
__device__ int   g_bsums[NB1];
__device__ int2  g_edge[NEDGES];
__device__ __half g_h1h[(size_t)NNODES * 128];   // layer-1 GEMM out (fp16)
__device__ __half g_a1h[(size_t)NNODES * 128];   // relu(agg1) = layer-2 input (fp16)
__device__ __half g_h2h[(size_t)NNODES * 64];    // layer-2 GEMM out (fp16)
// fp16 W images: n-major, k-stride 136 halves (272 B)
__device__ __half g_w1img[128 * 136];
__device__ __half g_w2img[64 * 136];

// ---------------- mma helpers (portable PTX, no 'a' features) ----------------
__device__ __forceinline__ uint32_t smem_u32(const void* p) {
    uint32_t a;
    asm("{ .reg .u64 t; cvta.to.shared.u64 t, %1; cvt.u32.u64 %0, t; }" : "=r"(a) : "l"(p));
    return a;
}
#define LDSM_X4(r, addr) \
    asm volatile("ldmatrix.sync.aligned.m8n8.x4.shared.b16 {%0,%1,%2,%3}, [%4];" \
        : "=r"((r)[0]), "=r"((r)[1]), "=r"((r)[2]), "=r"((r)[3]) : "r"(addr))
#define MMA_F16(c, a, b0, b1) \
    asm volatile("mma.sync.aligned.m16n8k16.row.col.f32.f16.f16.f32 " \
        "{%0,%1,%2,%3}, {%4,%5,%6,%7}, {%8,%9}, {%0,%1,%2,%3};" \
        : "+f"((c)[0]), "+f"((c)[1]), "+f"((c)[2]), "+f"((c)[3]) \
        : "r"((a)[0]), "r"((a)[1]), "r"((a)[2]), "r"((a)[3]), \
          "r"(b0), "r"(b1))

__device__ __forceinline__ uint32_t pack_f16x2(float f0, float f1) {
    uint32_t r;
    asm("cvt.rn.f16x2.f32 %0, %1, %2;" : "=r"(r) : "f"(f1), "f"(f0));
    return r;   // low half = f16(f0), high half = f16(f1)
}

// ---------------- W convert/transpose into fp16 image ----------------
__global__ void k_wconv(const float* __restrict__ W1, const float* __restrict__ W2) {
    int t = blockIdx.x * 256 + threadIdx.x;
    if (t < 128 * 128) {                     // W1[k][n]
        int k = t >> 7, n = t & 127;
        g_w1img[n * 136 + k] = __float2half(W1[t]);
    } else if (t < 128 * 128 + 128 * 64) {   // W2[k][n]
        int u = t - 128 * 128;
        int k = u >> 6, n = u & 63;
        g_w2img[n * 136 + k] = __float2half(W2[u]);
    }
}

// ---------------- init (+ fused edge_index dtype detection) ----------------
__global__ void k_init(const int* __restrict__ ei_raw) {
    int i = blockIdx.x * 256 + threadIdx.x;
    if (i < NNODES) { g_deg[i] = 1.0f; g_hist[i] = 0; }
    if (blockIdx.x == 0) {
        int bad = 0;
        for (int k = threadIdx.x; k < 2048; k += 256)
            bad |= (ei_raw[2 * k + 1] != 0);
        bad = __syncthreads_or(bad);
        if (threadIdx.x == 0) g_is64 = !bad;
    }
}

__device__ __forceinline__ void load_edge(const void* __restrict__ ei, int e,
                                          int& s, int& d) {
    if (g_is64) {
        const long long* p = (const long long*)ei;
        s = (int)p[e]; d = (int)p[NEDGES + e];
    } else {
        const int* p = (const int*)ei;
        s = p[e]; d = p[NEDGES + e];
    }
}

__global__ void k_deg(const void* __restrict__ ei, const float* __restrict__ ew) {
    int e = blockIdx.x * 256 + threadIdx.x;
    if (e < NEDGES) {
        int s, d; load_edge(ei, e, s, d);
        atomicAdd(&g_deg[d], ew[e]);
        atomicAdd(&g_hist[d], 1);
    }
}

__global__ void k_scan1() {
    __shared__ int sh[256];
    int i = blockIdx.x * 256 + threadIdx.x;
    int tid = threadIdx.x;
    if (i < NNODES) g_dis[i] = rsqrtf(g_deg[i]);
    int v = (i < NNODES) ? g_hist[i] : 0;
    sh[tid] = v; __syncthreads();
    for (int off = 1; off < 256; off <<= 1) {
        int t = (tid >= off) ? sh[tid - off] : 0;
        __syncthreads(); sh[tid] += t; __syncthreads();
    }
    if (i < NNODES) g_row[i] = sh[tid] - v;
    if (tid == 255) g_bsums[blockIdx.x] = sh[tid];
}

__global__ void k_scan2() {
    __shared__ int sh[512];
    int tid = threadIdx.x;
    int v = (tid < NB1) ? g_bsums[tid] : 0;
    sh[tid] = v; __syncthreads();
    for (int off = 1; off < 512; off <<= 1) {
        int t = (tid >= off) ? sh[tid - off] : 0;
        __syncthreads(); sh[tid] += t; __syncthreads();
    }
    if (tid < NB1) g_bsums[tid] = sh[tid] - v;
}

__global__ void k_scan3() {
    int i = blockIdx.x * 256 + threadIdx.x;
    if (i < NNODES) {
        int r = g_row[i] + g_bsums[blockIdx.x];
        g_row[i] = r;
        g_cursor[i] = r;
        if (i == 0) g_row[NNODES] = NEDGES;
    }
}

__global__ void k_sort(const void* __restrict__ ei, const float* __restrict__ ew) {
    int e = blockIdx.x * 256 + threadIdx.x;
    if (e < NEDGES) {
        int s, d; load_edge(ei, e, s, d);
        float nrm = g_dis[s] * ew[e] * g_dis[d];
        int pos = atomicAdd(&g_cursor[d], 1);
        g_edge[pos] = make_int2(s, __float_as_int(nrm));
    }
}

// ---------------- tensor-core GEMM (fp16 1-pass): H = X @ W ----------------
template<int NCOL, int LAYER>
__global__ __launch_bounds__(256, 2) void gemm_mma(
    const float* __restrict__ Xin, int M)
{
    constexpr int STR = 272;                 // bytes per fp16 row (136 halves)
    constexpr int XT  = 128 * STR;           // 34816 B X tile
    constexpr int WT  = NCOL * STR;          // W tile bytes
    constexpr int NF  = NCOL / 8;            // n-frags per warp (16 or 8)

    extern __shared__ __align__(16) char smem[];
    char* xs = smem;
    char* ws = xs + XT;

    __half* __restrict__ H = (LAYER == 1) ? g_h1h : g_h2h;

    const int tid  = threadIdx.x;
    const int lane = tid & 31;
    const int wid  = tid >> 5;
    const int row0 = blockIdx.x * 128;
    const int valid = M - row0;

    if (LAYER == 1) {
        for (int u = tid; u < 128 * 32; u += 256) {
            int r = u >> 5, c4 = u & 31;
            float4 v = make_float4(0.f, 0.f, 0.f, 0.f);
            if (r < valid)
                v = reinterpret_cast<const float4*>(Xin)[(size_t)(row0 + r) * 32 + c4];
            uint2 p;
            p.x = pack_f16x2(v.x, v.y);
            p.y = pack_f16x2(v.z, v.w);
            *reinterpret_cast<uint2*>(xs + r * STR + c4 * 8) = p;
        }
    } else {
        const uint4* A = reinterpret_cast<const uint4*>(g_a1h);
        for (int u = tid; u < 128 * 16; u += 256) {
            int r = u >> 4, c = u & 15;
            uint4 v = make_uint4(0u, 0u, 0u, 0u);
            if (r < valid)
                v = A[(size_t)(row0 + r) * 16 + c];
            *reinterpret_cast<uint4*>(xs + r * STR + c * 16) = v;
        }
    }
    {
        const uint4* wsrc = (LAYER == 1)
            ? reinterpret_cast<const uint4*>(g_w1img)
            : reinterpret_cast<const uint4*>(g_w2img);
        uint4* wdst = reinterpret_cast<uint4*>(ws);
        for (int u = tid; u < WT / 16; u += 256)
            wdst[u] = wsrc[u];
    }
    __syncthreads();

    const int mb = wid * 16;
    int a_row = mb + (lane & 7) + ((lane >> 3) & 1) * 8;
    uint32_t ah_base = smem_u32(xs) + a_row * STR + ((lane >> 4) & 1) * 16;
    uint32_t b_base = smem_u32(ws)
                    + (((lane >> 4) & 1) * 8 + (lane & 7)) * STR
                    + ((lane >> 3) & 1) * 16;

    float c[NF][4];
#pragma unroll
    for (int nf = 0; nf < NF; nf++)
#pragma unroll
        for (int q = 0; q < 4; q++) c[nf][q] = 0.f;

#pragma unroll
    for (int ks = 0; ks < 8; ks++) {
        uint32_t a[4];
        LDSM_X4(a, ah_base + ks * 32);
#pragma unroll
        for (int np = 0; np < NF / 2; np++) {
            uint32_t b[4];
            LDSM_X4(b, b_base + np * 16 * STR + ks * 32);
            MMA_F16(c[2 * np],     a, b[0], b[1]);
            MMA_F16(c[2 * np + 1], a, b[2], b[3]);
        }
    }

    uint32_t* Hu = reinterpret_cast<uint32_t*>(H);
    int r0 = row0 + mb + (lane >> 2);
    int cq = lane & 3;
#pragma unroll
    for (int nf = 0; nf < NF; nf++) {
        if (r0 < M)
            Hu[(size_t)r0 * (NCOL / 2) + nf * 4 + cq] = pack_f16x2(c[nf][0], c[nf][1]);
        if (r0 + 8 < M)
            Hu[(size_t)(r0 + 8) * (NCOL / 2) + nf * 4 + cq] = pack_f16x2(c[nf][2], c[nf][3]);
    }
}

// ---------------- segmented aggregation: one warp per dst node --------------
__global__ __launch_bounds__(256) void agg1(const float* __restrict__ bias) {
    int w = (blockIdx.x * 256 + threadIdx.x) >> 5;
    int lane = threadIdx.x & 31;
    if (w >= NNODES) return;
    const uint2* H = reinterpret_cast<const uint2*>(g_h1h);

    int beg = g_row[w], end = g_row[w + 1];
    float ds = g_dis[w];
    float s2 = ds * ds;

    uint2 hv = H[(size_t)w * 32 + lane];
    float2 f0 = __half22float2(*reinterpret_cast<__half2*>(&hv.x));
    float2 f1 = __half22float2(*reinterpret_cast<__half2*>(&hv.y));
    float a0 = s2 * f0.x, a1 = s2 * f0.y, a2 = s2 * f1.x, a3 = s2 * f1.y;

    for (int e = beg; e < end; e++) {
        int2 md = g_edge[e];
        float nm = __int_as_float(md.y);
        uint2 v = H[(size_t)md.x * 32 + lane];
        float2 g0 = __half22float2(*reinterpret_cast<__half2*>(&v.x));
        float2 g1 = __half22float2(*reinterpret_cast<__half2*>(&v.y));
        a0 = fmaf(nm, g0.x, a0);
        a1 = fmaf(nm, g0.y, a1);
        a2 = fmaf(nm, g1.x, a2);
        a3 = fmaf(nm, g1.y, a3);
    }
    float4 bv = reinterpret_cast<const float4*>(bias)[lane];
    a0 = fmaxf(a0 + bv.x, 0.f);
    a1 = fmaxf(a1 + bv.y, 0.f);
    a2 = fmaxf(a2 + bv.z, 0.f);
    a3 = fmaxf(a3 + bv.w, 0.f);
    uint2 o;
    o.x = pack_f16x2(a0, a1);
    o.y = pack_f16x2(a2, a3);
    reinterpret_cast<uint2*>(g_a1h)[(size_t)w * 32 + lane] = o;
}

__global__ __launch_bounds__(256) void agg2(const float* __restrict__ bias,
                                            float* __restrict__ out) {
    int w = (blockIdx.x * 256 + threadIdx.x) >> 5;
    int lane = threadIdx.x & 31;
    if (w >= NNODES) return;
    const uint32_t* H = reinterpret_cast<const uint32_t*>(g_h2h);

    int beg = g_row[w], end = g_row[w + 1];
    float ds = g_dis[w];
    float s2 = ds * ds;

    uint32_t hv = H[(size_t)w * 32 + lane];
    float2 f = __half22float2(*reinterpret_cast<__half2*>(&hv));
    float a0 = s2 * f.x, a1 = s2 * f.y;

    for (int e = beg; e < end; e++) {
        int2 md = g_edge[e];
        float nm = __int_as_float(md.y);
        uint32_t v = H[(size_t)md.x * 32 + lane];
        float2 g = __half22float2(*reinterpret_cast<__half2*>(&v));
        a0 = fmaf(nm, g.x, a0);
        a1 = fmaf(nm, g.y, a1);
    }
    float2 bv = reinterpret_cast<const float2*>(bias)[lane];
    float2 o = make_float2(a0 + bv.x, a1 + bv.y);
    reinterpret_cast<float2*>(out)[(size_t)w * 32 + lane] = o;
}

// ---------------- launch (two-stream fork/join, graph-capturable) ----------
extern "C" void kernel_launch(void* const* d_in, const int* in_sizes, int n_in,
                              void* d_out, int out_size)
{
    const float* x  = (const float*)d_in[0];
    const void*  ei = d_in[1];
    const float* ew = (const float*)d_in[2];
    const float* W1 = (const float*)d_in[3];
    const float* b1 = (const float*)d_in[4];
    const float* W2 = (const float*)d_in[5];
    const float* b2 = (const float*)d_in[6];
    float* out = (float*)d_out;

    const int nb_nodes = (NNODES + 255) / 256;
    const int nb_edges = (NEDGES + 255) / 256;
    const int nb_rows  = (NNODES + 127) / 128;   // 782
    const int nb_warps = (NNODES * 32 + 255) / 256;

    constexpr int SM1 = 128 * 272 + 128 * 272;   // 69632 B
    constexpr int SM2 = 128 * 272 + 64 * 272;    // 52224 B

    // one-time infra (created on the uncaptured correctness call)
    static cudaStream_t s1 = nullptr;
    static cudaEvent_t evFork = nullptr, evJoin = nullptr;
    if (!s1) {
        cudaFuncSetAttribute(gemm_mma<128, 1>,
                             cudaFuncAttributeMaxDynamicSharedMemorySize, SM1);
        cudaFuncSetAttribute(gemm_mma<64, 2>,
                             cudaFuncAttributeMaxDynamicSharedMemorySize, SM2);
        cudaStreamCreateWithFlags(&s1, cudaStreamNonBlocking);
        cudaEventCreateWithFlags(&evFork, cudaEventDisableTiming);
        cudaEventCreateWithFlags(&evJoin, cudaEventDisableTiming);
    }

    // fork: branch B (CSR build) on s1, branch A (wconv+gemm1) on capture stream
    cudaEventRecord(evFork, 0);
    cudaStreamWaitEvent(s1, evFork, 0);

    k_init<<<nb_nodes, 256, 0, s1>>>((const int*)ei);            // 0
    k_deg<<<nb_edges, 256, 0, s1>>>(ei, ew);                     // 1
    k_wconv<<<96, 256>>>(W1, W2);                                // 2
    gemm_mma<128, 1><<<nb_rows, 256, SM1>>>(x, NNODES);          // 3 <- profiled
    k_scan1<<<nb_nodes, 256, 0, s1>>>();                         // 4
    k_scan2<<<1, 512, 0, s1>>>();                                // 5
    k_scan3<<<nb_nodes, 256, 0, s1>>>();                         // 6
    k_sort<<<nb_edges, 256, 0, s1>>>(ei, ew);                    // 7

    // join: serial tail needs both branches
    cudaEventRecord(evJoin, s1);
    cudaStreamWaitEvent(0, evJoin, 0);

    agg1<<<nb_warps, 256>>>(b1);                                 // 8
    gemm_mma<64, 2><<<nb_rows, 256, SM2>>>(nullptr, NNODES);     // 9
    agg2<<<nb_warps, 256>>>(b2, out);                            // 10
}